// round 17
// baseline (speedup 1.0000x reference)
#include <cuda_runtime.h>
#include <cuda_fp16.h>
#include <cstdint>

#define S_DIM 4
#define N_DIM 4096
#define D_DIM 64

// fp32 scratch for Q[s,j,d] = sum_e x0[s,j,e] * W[d,e]
__device__ float g_Q[S_DIM * N_DIM * D_DIM];

__device__ __forceinline__ uint32_t smem_u32(const void* p) {
    uint32_t a;
    asm("{ .reg .u64 t; cvta.to.shared.u64 t, %1; cvt.u32.u64 %0, t; }"
        : "=r"(a) : "l"(p));
    return a;
}
__device__ __forceinline__ uint32_t h2pack(float a, float b) {
    __half2 h = __floats2half2_rn(a, b);
    return *reinterpret_cast<uint32_t*>(&h);
}
// fp16 mma m16n8k16, fp32 accumulate (baseline PTX, valid on compute_103)
__device__ __forceinline__ void mma_fp16(float d[4], const uint32_t a[4], const uint32_t b[2]) {
    asm volatile(
        "mma.sync.aligned.m16n8k16.row.col.f32.f16.f16.f32 "
        "{%0,%1,%2,%3}, {%4,%5,%6,%7}, {%8,%9}, {%0,%1,%2,%3};"
        : "+f"(d[0]), "+f"(d[1]), "+f"(d[2]), "+f"(d[3])
        : "r"(a[0]), "r"(a[1]), "r"(a[2]), "r"(a[3]), "r"(b[0]), "r"(b[1]));
}
__device__ __forceinline__ void ldsm_x4(uint32_t r[4], uint32_t addr) {
    asm volatile("ldmatrix.sync.aligned.m8n8.x4.shared.b16 {%0,%1,%2,%3}, [%4];"
                 : "=r"(r[0]), "=r"(r[1]), "=r"(r[2]), "=r"(r[3]) : "r"(addr));
}
__device__ __forceinline__ void ldsm_x2(uint32_t r[2], uint32_t addr) {
    asm volatile("ldmatrix.sync.aligned.m8n8.x2.shared.b16 {%0,%1}, [%2];"
                 : "=r"(r[0]), "=r"(r[1]) : "r"(addr));
}

// ---------------------------------------------------------------------------
// Prep: Q = x0 · Wᵀ only (fp32 SIMT, 64x64 tiles, fp32 output).
// x1 is consumed directly by the GEMM (fill-time fp16 conversion).
// ---------------------------------------------------------------------------
__device__ __forceinline__ void load_tile_transposed64(
    const float* __restrict__ gsrc, float* sdst, int t)
{
    const float4* g4 = reinterpret_cast<const float4*>(gsrc);
#pragma unroll
    for (int p = 0; p < 4; ++p) {
        int f4 = p * 256 + t;
        int x  = f4 >> 4;
        int k4 = (f4 & 15) << 2;
        float4 v = g4[f4];
        float vv[4] = {v.x, v.y, v.z, v.w};
#pragma unroll
        for (int q = 0; q < 4; ++q) {
            int k  = k4 + q;
            int c4 = (x >> 2) ^ ((k >> 2) & 15);
            sdst[k * 64 + c4 * 4 + (x & 3)] = vv[q];
        }
    }
}

__global__ __launch_bounds__(256) void prep_kernel(
    const float* __restrict__ x0, const float* __restrict__ W)
{
    __shared__ float Xs[64 * 64];
    __shared__ float Ws[64 * 64];
    int t  = threadIdx.x;
    int r0 = blockIdx.x * 64;

    load_tile_transposed64(x0 + (size_t)r0 * 64, Xs, t);
    load_tile_transposed64(W, Ws, t);
    __syncthreads();

    int tx = t & 15, ty = t >> 4;
    float acc[4][4] = {};
#pragma unroll
    for (int k = 0; k < 64; ++k) {
        int sw = (k >> 2) & 15;
        float4 a = *reinterpret_cast<const float4*>(&Xs[k * 64 + ((ty ^ sw) << 2)]);
        float4 b = *reinterpret_cast<const float4*>(&Ws[k * 64 + ((tx ^ sw) << 2)]);
        float av[4] = {a.x, a.y, a.z, a.w};
        float bv[4] = {b.x, b.y, b.z, b.w};
#pragma unroll
        for (int ra = 0; ra < 4; ++ra)
#pragma unroll
            for (int rb = 0; rb < 4; ++rb)
                acc[ra][rb] += av[ra] * bv[rb];
    }

#pragma unroll
    for (int ra = 0; ra < 4; ++ra) {
        int r = r0 + ty * 4 + ra;
        float4 v = make_float4(acc[ra][0], acc[ra][1], acc[ra][2], acc[ra][3]);
        *reinterpret_cast<float4*>(&g_Q[(size_t)r * 64 + tx * 4]) = v;
    }
}

// ---------------------------------------------------------------------------
// Stage 2 (round-13 optimum body): single-pass fp16 mma.sync GEMM, half-outer.
// Operand fills read fp32 (x1 / g_Q) and convert to fp16 pair-words in
// registers during the smem fill (LDG.128 -> 2x cvt -> STS.64, bank-clean).
// CTA = 128x128 C tile, 256 threads = 8 warps (2m x 4n), warp = 64x32.
// 32-reg accumulator -> 3 CTAs/SM. Plain 4096-CTA grid.
// Smem: 2 operand tiles [128][36 pair-words] (36.9 KB) + stage 64x136 fp32
// (34 KB) = 70.9 KB; x3 CTAs = 213 KB.
// ---------------------------------------------------------------------------
#define PADW 36
#define TILE_W (128 * PADW)
#define STG_STRIDE 136                  // floats per staged row (bank-safe)
#define STAGE_FLOATS (64 * STG_STRIDE)
#define SMEM_DYN (2 * TILE_W * 4 + STAGE_FLOATS * 4)
#define A_MT_BYTES (16 * PADW * 4)      // 16 rows
#define B_NT_BYTES (8 * PADW * 4)       // 8 rows
#define KT_BYTES   32                   // 8 pair-words = 16 fp16

// Load a 128x64 fp32 tile and store as fp16 pair-words (row-major, PADW stride)
__device__ __forceinline__ void fill_tile_cvt(
    const float* __restrict__ gsrc, uint32_t* sdst, int t)
{
    const float4* g4 = reinterpret_cast<const float4*>(gsrc);
#pragma unroll
    for (int it = 0; it < 8; ++it) {
        int f4 = it * 256 + t;          // 0..2047 float4s (128 rows x 16)
        float4 v = g4[f4];
        uint2 p;
        p.x = h2pack(v.x, v.y);
        p.y = h2pack(v.z, v.w);
        int r  = f4 >> 4;
        int c4 = f4 & 15;
        *reinterpret_cast<uint2*>(&sdst[r * PADW + c4 * 2]) = p;
    }
}

__global__ __launch_bounds__(256, 3) void bilinear_mma_kernel(
    const float* __restrict__ x1, const float* __restrict__ bias,
    float* __restrict__ out)
{
    extern __shared__ uint32_t sm[];
    uint32_t* Af = sm;
    uint32_t* Bf = sm + TILE_W;
    float* stage = reinterpret_cast<float*>(sm + 2 * TILE_W);

    int t    = threadIdx.x;
    int warp = t >> 5;
    int lane = t & 31;
    int wm   = warp >> 2;      // 0..1  (m, 64 rows)
    int wn   = warp & 3;       // 0..3  (n, 32 cols)
    int g    = lane >> 2;      // 0..7
    int tg   = lane & 3;       // 0..3

    int s  = blockIdx.z;
    int i0 = blockIdx.y * 128;
    int j0 = blockIdx.x * 128;

    fill_tile_cvt(x1  + ((size_t)s * N_DIM + i0) * D_DIM, Af, t);
    fill_tile_cvt(g_Q + ((size_t)s * N_DIM + j0) * D_DIM, Bf, t);
    __syncthreads();

    // ldmatrix per-lane row addressing (b16 elements)
    int rowA   = (lane & 7) + 8 * ((lane >> 3) & 1);
    int kplusA = (lane >> 4) & 1;
    int rowB   = lane & 7;
    int kplusB = (lane >> 3) & 1;

    uint32_t aAf = smem_u32(Af) + ((wm * 64 + rowA) * PADW + kplusA * 4) * 4;
    uint32_t aBf = smem_u32(Bf) + ((wn * 32 + rowB) * PADW + kplusB * 4) * 4;

    float bv = __ldg(bias);
    const size_t batch_stride = (size_t)S_DIM * N_DIM * N_DIM;

#pragma unroll
    for (int hf = 0; hf < 2; ++hf) {
        // ---- compute half: mt = 2hf, 2hf+1 ----
        float acc[2][4][4];
#pragma unroll
        for (int a = 0; a < 2; ++a)
#pragma unroll
            for (int b = 0; b < 4; ++b)
#pragma unroll
                for (int c = 0; c < 4; ++c) acc[a][b][c] = 0.0f;

#pragma unroll
        for (int kt = 0; kt < 4; ++kt) {
            uint32_t af[2][4];
            uint32_t bf[4][2];
#pragma unroll
            for (int m = 0; m < 2; ++m)
                ldsm_x4(af[m], aAf + (2 * hf + m) * A_MT_BYTES + kt * KT_BYTES);
#pragma unroll
            for (int nt = 0; nt < 4; ++nt)
                ldsm_x2(bf[nt], aBf + nt * B_NT_BYTES + kt * KT_BYTES);

#pragma unroll
            for (int m = 0; m < 2; ++m)
#pragma unroll
                for (int nt = 0; nt < 4; ++nt)
                    mma_fp16(acc[m][nt], af[m], bf[nt]);
        }

        // ---- store half via stage ----
        __syncthreads();   // stage free (prev half's readers done)
#pragma unroll
        for (int m = 0; m < 2; ++m) {
#pragma unroll
            for (int h = 0; h < 2; ++h) {
                int L = wm * 32 + m * 16 + g + 8 * h;
#pragma unroll
                for (int nt = 0; nt < 4; ++nt) {
                    float2 v;
                    v.x = acc[m][nt][2 * h + 0] + bv;
                    v.y = acc[m][nt][2 * h + 1] + bv;
                    *reinterpret_cast<float2*>(
                        &stage[L * STG_STRIDE + wn * 32 + nt * 8 + 2 * tg]) = v;
                }
            }
        }
        __syncthreads();
        // Coalesced: warp reads full 128-float rows, 512B STG.128 runs
#pragma unroll
        for (int rr = 0; rr < 8; ++rr) {
            int L = warp + rr * 8;      // 0..63
            int irel = ((L >> 5) << 6) + ((2 * hf + ((L >> 4) & 1)) << 4) + (L & 15);
            size_t rowoff = ((size_t)s * N_DIM + i0 + irel) * N_DIM + j0;
            float4 v = *reinterpret_cast<float4*>(&stage[L * STG_STRIDE + lane * 4]);
            __stcs(reinterpret_cast<float4*>(&out[rowoff + lane * 4]), v);
            __stcs(reinterpret_cast<float4*>(&out[rowoff + lane * 4 + batch_stride]), v);
        }
    }
}

extern "C" void kernel_launch(void* const* d_in, const int* in_sizes, int n_in,
                              void* d_out, int out_size)
{
    const float* x0   = (const float*)d_in[0];  // tensor0 (S,N,D)
    const float* x1   = (const float*)d_in[1];  // tensor1 (S,N,D)
    const float* W    = (const float*)d_in[2];  // kernel  (D,D)
    const float* bias = (const float*)d_in[3];  // scalar
    float* out = (float*)d_out;                 // (2,S,N,N)

    cudaFuncSetAttribute(bilinear_mma_kernel,
                         cudaFuncAttributeMaxDynamicSharedMemorySize, SMEM_DYN);

    prep_kernel<<<(S_DIM * N_DIM) / 64, 256>>>(x0, W);

    dim3 grid(N_DIM / 128, N_DIM / 128, S_DIM);
    bilinear_mma_kernel<<<grid, 256, SMEM_DYN>>>(x1, bias, out);
}